// round 14
// baseline (speedup 1.0000x reference)
#include <cuda_runtime.h>
#include <math.h>

#define D 128
#define SEGS 32
#define SROWS 32            // rows per seg_sum block (3125 blocks — proven best)
#define GROWS 64            // rows per gate block

// Scratch — zero-initialized at module load; the fused kernel self-restores
// all mutable state every launch (correctness, capture, replay all clean).
__device__ __align__(16) float g_sums[SEGS * D];
__device__ float g_cnt[SEGS];
__device__ __align__(16) float g_gateV[SEGS * D];
__device__ __align__(16) float g_gateE[SEGS * D];
__device__ unsigned int g_done  = 0;   // seg blocks finished
__device__ unsigned int g_done2 = 0;   // mlp blocks finished

// ---------------------------------------------------------------------------
__device__ __forceinline__ void prefetch_l2(const void* p, int bytes, int t) {
    for (int off = t * 128; off < bytes; off += 256 * 128)
        asm volatile("prefetch.global.L2 [%0];" :: "l"((const char*)p + off));
}

// 256-thread MLP layer: each output's 128-dot split in 2 halves (64 FMAs).
__device__ __forceinline__ void mlp_layer256(
    const float* __restrict__ sin, float* __restrict__ sout,
    const float* __restrict__ W, const float* __restrict__ b,
    float* __restrict__ sred, int t128, int part, bool do_relu) {
    float p = 0.0f;
    const float* Wp = W + (part * 64) * D + t128;
    const float* xp = sin + part * 64;
#pragma unroll
    for (int k = 0; k < 64; k++)
        p = fmaf(xp[k], __ldg(&Wp[k * D]), p);
    sred[part * D + t128] = p;
    __syncthreads();
    if (part == 0) {
        float v = sred[t128] + sred[D + t128] + __ldg(&b[t128]);
        sout[t128] = do_relu ? fmaxf(v, 0.0f) : v;
    }
    __syncthreads();
}

// ---------------------------------------------------------------------------
// Fused seg-sum + MLP, one launch.
//   blocks [0, sumBlocks): segment sums (32 rows, 4 front-batched float4
//     loads issued BEFORE the bid branch — R12-proven), then bump g_done.
//   blocks [sumBlocks, sumBlocks+SEGS): scheduled in the last wave; prefetch
//     MLP weights into L2 while seg blocks drain, spin on g_done, compute
//     both gate MLPs on warm weights, reset scratch + counters.
__global__ void __launch_bounds__(256) seg_mlp_kernel(
    const float* __restrict__ x, const int* __restrict__ bid, int N,
    int sumBlocks,
    const float* __restrict__ VW1, const float* __restrict__ Vb1,
    const float* __restrict__ VW2, const float* __restrict__ Vb2,
    const float* __restrict__ VW3, const float* __restrict__ Vb3,
    const float* __restrict__ EW1, const float* __restrict__ Eb1,
    const float* __restrict__ EW2, const float* __restrict__ Eb2,
    const float* __restrict__ EW3, const float* __restrict__ Eb3) {
    __shared__ float pool[8 * D];          // 4 KB, role-dependent layout
    int b = blockIdx.x;
    int t = threadIdx.x;

    if (b < sumBlocks) {
        // ---------------- segment-sum role ----------------
        int r0 = b * SROWS;
        int rlast = min(r0 + SROWS, N) - 1;

        int f4c = t & 31;            // float4 column 0..31
        int rg  = t >> 5;            // row group 0..7
        const float4* xf4 = (const float4*)x;   // 32 float4 per row
        size_t base = (size_t)(r0 + rg) * 32 + f4c;

        // Data loads FIRST (independent of bid) — 4 front-batched LDG.128.
        float4 a0, a1, a2, a3;
        if (r0 + SROWS <= N) {
            a0 = xf4[base];
            a1 = xf4[base + 8 * 32];
            a2 = xf4[base + 16 * 32];
            a3 = xf4[base + 24 * 32];
        } else {
            float4 z = make_float4(0.f, 0.f, 0.f, 0.f);
            a0 = (r0 + rg      < N) ? xf4[base]           : z;
            a1 = (r0 + rg + 8  < N) ? xf4[base + 8 * 32]  : z;
            a2 = (r0 + rg + 16 < N) ? xf4[base + 16 * 32] : z;
            a3 = (r0 + rg + 24 < N) ? xf4[base + 24 * 32] : z;
        }

        // Branch condition resolves under the shadow of the data loads.
        int s0 = __ldg(&bid[r0]);
        int s1 = __ldg(&bid[rlast]);

        if (s0 == s1) {
            float (*sred)[D] = (float(*)[D])pool;
            float4 acc;
            acc.x = (a0.x + a1.x) + (a2.x + a3.x);
            acc.y = (a0.y + a1.y) + (a2.y + a3.y);
            acc.z = (a0.z + a1.z) + (a2.z + a3.z);
            acc.w = (a0.w + a1.w) + (a2.w + a3.w);
            *(float4*)&sred[rg][f4c * 4] = acc;
            __syncthreads();
            if (t < D) {
                float s = (sred[0][t] + sred[1][t]) + (sred[2][t] + sred[3][t])
                        + (sred[4][t] + sred[5][t]) + (sred[6][t] + sred[7][t]);
                atomicAdd(&g_sums[s0 * D + t], s);
                if (t == 0) atomicAdd(&g_cnt[s0], (float)(rlast - r0 + 1));
            }
        } else {
            // slow path: segment boundary inside block (~1% of blocks);
            // rows are L2-hot from the speculative loads above.
            if (t < D) {
                float acc = 0.0f, cnt = 0.0f;
                int cur = s0;
                for (int r = r0; r <= rlast; r++) {
                    int s = __ldg(&bid[r]);
                    if (s != cur) {
                        atomicAdd(&g_sums[cur * D + t], acc);
                        if (t == 0) atomicAdd(&g_cnt[cur], cnt);
                        acc = 0.0f; cnt = 0.0f; cur = s;
                    }
                    acc += x[(size_t)r * D + t];
                    cnt += 1.0f;
                }
                atomicAdd(&g_sums[cur * D + t], acc);
                if (t == 0) atomicAdd(&g_cnt[cur], cnt);
            }
        }
        // release: this block's atomics precede the counter bump
        __syncthreads();
        if (t == 0) {
            __threadfence();
            atomicAdd(&g_done, 1u);
        }
        return;
    }

    // ---------------- MLP role (32 tail blocks, one per segment) ----------
    int seg = b - sumBlocks;

    // Warm the weights into L2 while remaining seg blocks drain.
    {
        const float* Ws[6] = {VW1, VW2, VW3, EW1, EW2, EW3};
        prefetch_l2(Ws[seg % 6], D * D * 4, t);
    }

    if (t == 0) {
        while (atomicAdd(&g_done, 0u) < (unsigned)sumBlocks) __nanosleep(32);
        __threadfence();   // acquire
    }
    __syncthreads();

    float* scv  = pool;
    float* bufA = pool + D;
    float* bufB = pool + 2 * D;
    float* sred = pool + 3 * D;            // 2*D
    int t128 = t & 127;
    int part = t >> 7;

    if (t < D) {
        float cnt = fmaxf(g_cnt[seg], 1.0f);
        scv[t] = g_sums[seg * D + t] / cnt;   // c_V
    }
    __syncthreads();

    // --- V MLP ---
    mlp_layer256(scv,  bufA, VW1, Vb1, sred, t128, part, true);
    mlp_layer256(bufA, bufB, VW2, Vb2, sred, t128, part, true);
    mlp_layer256(bufB, bufA, VW3, Vb3, sred, t128, part, false);
    if (t < D) {
        float gV = 1.0f / (1.0f + expf(-bufA[t]));
        g_gateV[seg * D + t] = gV;
        bufB[t] = scv[t] * gV;     // c_V2 = c_V * gate_V (exact identity)
    }
    __syncthreads();

    // --- E MLP ---
    mlp_layer256(bufB, bufA, EW1, Eb1, sred, t128, part, true);
    mlp_layer256(bufA, bufB, EW2, Eb2, sred, t128, part, true);
    mlp_layer256(bufB, bufA, EW3, Eb3, sred, t128, part, false);
    if (t < D) {
        g_gateE[seg * D + t] = 1.0f / (1.0f + expf(-bufA[t]));
        // restore scratch for the next launch (zero-invariant at entry)
        g_sums[seg * D + t] = 0.0f;
        if (t == 0) g_cnt[seg] = 0.0f;
    }
    __syncthreads();
    if (t == 0) {
        __threadfence();
        unsigned o = atomicAdd(&g_done2, 1u);
        if (o == SEGS - 1) {       // last MLP block: all spins finished
            g_done  = 0u;          // reset for next launch/replay
            g_done2 = 0u;
        }
    }
}

// ---------------------------------------------------------------------------
// Gating. Blocks [0, nodeBlocks) gate nodes (dst_na L2-warm from seg_sum);
// rest gate edges. 64 rows/block, 8 float4 iters; warp-uniform row ->
// bid/eidx loads broadcast. Edges stream with __ldcs/__stcs.
__global__ void __launch_bounds__(256) gate_kernel(
    const float* __restrict__ x, const float* __restrict__ ea,
    const int* __restrict__ eidx, const int* __restrict__ bid,
    float* __restrict__ outN, float* __restrict__ outE,
    int N, int E, int nodeBlocks) {
    int t = threadIdx.x;
    int b = blockIdx.x;

    if (b < nodeBlocks) {
        int r0 = b * GROWS;
        const float4* src = (const float4*)x;
        float4* dst = (float4*)outN;
        long long base = (long long)r0 * 32;
#pragma unroll
        for (int it = 0; it < 8; it++) {
            int i = it * 256 + t;
            int r = r0 + (i >> 5);             // warp-uniform
            if (r < N) {
                int s = __ldg(&bid[r]);        // broadcast
                float4 g = *(const float4*)&g_gateV[s * D + (i & 31) * 4];
                float4 v = src[base + i];
                v.x *= g.x; v.y *= g.y; v.z *= g.z; v.w *= g.w;
                __stcs(&dst[base + i], v);
            }
        }
    } else {
        int r0 = (b - nodeBlocks) * GROWS;
        const float4* src = (const float4*)ea;
        float4* dst = (float4*)outE;
        long long base = (long long)r0 * 32;
#pragma unroll
        for (int it = 0; it < 8; it++) {
            int i = it * 256 + t;
            int r = r0 + (i >> 5);             // warp-uniform
            if (r < E) {
                int s = __ldg(&bid[__ldg(&eidx[r])]);   // 2 broadcasts
                float4 g = *(const float4*)&g_gateE[s * D + (i & 31) * 4];
                float4 v = __ldcs(&src[base + i]);
                v.x *= g.x; v.y *= g.y; v.z *= g.z; v.w *= g.w;
                __stcs(&dst[base + i], v);
            }
        }
    }
}

// ---------------------------------------------------------------------------
extern "C" void kernel_launch(void* const* d_in, const int* in_sizes, int n_in,
                              void* d_out, int out_size) {
    const float* dst_na  = (const float*)d_in[0];
    const float* ea      = (const float*)d_in[1];
    const int*   eidx    = (const int*)d_in[2];   // [2, E], row 0 = src
    const int*   bid     = (const int*)d_in[3];
    const float* VW1 = (const float*)d_in[4];
    const float* Vb1 = (const float*)d_in[5];
    const float* VW2 = (const float*)d_in[6];
    const float* Vb2 = (const float*)d_in[7];
    const float* VW3 = (const float*)d_in[8];
    const float* Vb3 = (const float*)d_in[9];
    const float* EW1 = (const float*)d_in[10];
    const float* Eb1 = (const float*)d_in[11];
    const float* EW2 = (const float*)d_in[12];
    const float* Eb2 = (const float*)d_in[13];
    const float* EW3 = (const float*)d_in[14];
    const float* Eb3 = (const float*)d_in[15];

    int N = in_sizes[0] / D;
    int E = in_sizes[1] / D;
    float* out_nodes = (float*)d_out;
    float* out_edges = (float*)d_out + (size_t)N * D;

    int sumBlocks = (N + SROWS - 1) / SROWS;
    seg_mlp_kernel<<<sumBlocks + SEGS, 256>>>(
        dst_na, bid, N, sumBlocks,
        VW1, Vb1, VW2, Vb2, VW3, Vb3,
        EW1, Eb1, EW2, Eb2, EW3, Eb3);

    int nodeBlocks = (N + GROWS - 1) / GROWS;
    int edgeBlocks = (E + GROWS - 1) / GROWS;
    gate_kernel<<<nodeBlocks + edgeBlocks, 256>>>(
        dst_na, ea, eidx, bid, out_nodes, out_edges, N, E, nodeBlocks);
}

// round 15
// speedup vs baseline: 1.0881x; 1.0881x over previous
#include <cuda_runtime.h>
#include <math.h>

#define D 128
#define SEGS 32
#define SROWS 32            // rows per seg_sum block (3125 blocks — proven best)
#define GROWS 64            // rows per gate block

// Scratch — zero-initialized at module load; mlp_kernel re-zeroes at its end
// so every launch (correctness, capture, replay) starts clean.
__device__ __align__(16) float g_sums[SEGS * D];
__device__ float g_cnt[SEGS];
__device__ __align__(16) float g_gateV[SEGS * D];
__device__ __align__(16) float g_gateE[SEGS * D];

// ---------------------------------------------------------------------------
__device__ __forceinline__ void prefetch_l2(const void* p, int bytes, int t) {
    for (int off = t * 128; off < bytes; off += 256 * 128)
        asm volatile("prefetch.global.L2 [%0];" :: "l"((const char*)p + off));
}

// ---------------------------------------------------------------------------
// Segment sums over sorted batch_id. 256 threads per 32 rows -> 3125 blocks.
// Data loads issued BEFORE the bid branch (R12-proven: hides the per-block
// serial prelude). 6 tail blocks prefetch MLP weights into L2. Every block
// ends with a PDL trigger so the mlp launch overlaps this kernel's drain.
__global__ void __launch_bounds__(256) seg_sum_kernel(
    const float* __restrict__ x, const int* __restrict__ bid, int N,
    int sumBlocks,
    const float* __restrict__ VW1, const float* __restrict__ VW2,
    const float* __restrict__ VW3, const float* __restrict__ EW1,
    const float* __restrict__ EW2, const float* __restrict__ EW3) {
    int b = blockIdx.x;
    int t = threadIdx.x;

    if (b >= sumBlocks) {
        // weight-prefetch role (6 blocks, one matrix each)
        int role = b - sumBlocks;
        const float* Ws[6] = {VW1, VW2, VW3, EW1, EW2, EW3};
        if (role < 6) prefetch_l2(Ws[role], D * D * 4, t);
        cudaTriggerProgrammaticLaunchCompletion();
        return;
    }

    int r0 = b * SROWS;
    int rlast = min(r0 + SROWS, N) - 1;

    int f4c = t & 31;            // float4 column 0..31
    int rg  = t >> 5;            // row group 0..7
    const float4* xf4 = (const float4*)x;   // 32 float4 per row
    size_t base = (size_t)(r0 + rg) * 32 + f4c;

    // Data loads FIRST (independent of bid) — 4 front-batched LDG.128.
    float4 a0, a1, a2, a3;
    if (r0 + SROWS <= N) {
        a0 = xf4[base];
        a1 = xf4[base + 8 * 32];
        a2 = xf4[base + 16 * 32];
        a3 = xf4[base + 24 * 32];
    } else {
        float4 z = make_float4(0.f, 0.f, 0.f, 0.f);
        a0 = (r0 + rg      < N) ? xf4[base]           : z;
        a1 = (r0 + rg + 8  < N) ? xf4[base + 8 * 32]  : z;
        a2 = (r0 + rg + 16 < N) ? xf4[base + 16 * 32] : z;
        a3 = (r0 + rg + 24 < N) ? xf4[base + 24 * 32] : z;
    }

    // Branch condition resolves under the shadow of the data loads.
    int s0 = __ldg(&bid[r0]);
    int s1 = __ldg(&bid[rlast]);

    if (s0 == s1) {
        __shared__ float sred[8][D];
        float4 acc;
        acc.x = (a0.x + a1.x) + (a2.x + a3.x);
        acc.y = (a0.y + a1.y) + (a2.y + a3.y);
        acc.z = (a0.z + a1.z) + (a2.z + a3.z);
        acc.w = (a0.w + a1.w) + (a2.w + a3.w);
        *(float4*)&sred[rg][f4c * 4] = acc;
        __syncthreads();
        if (t < D) {
            float s = (sred[0][t] + sred[1][t]) + (sred[2][t] + sred[3][t])
                    + (sred[4][t] + sred[5][t]) + (sred[6][t] + sred[7][t]);
            atomicAdd(&g_sums[s0 * D + t], s);
            if (t == 0) atomicAdd(&g_cnt[s0], (float)(rlast - r0 + 1));
        }
    } else {
        // slow path: segment boundary inside block (~1% of blocks);
        // rows are L2-hot from the speculative loads above.
        if (t < D) {
            float acc = 0.0f, cnt = 0.0f;
            int cur = s0;
            for (int r = r0; r <= rlast; r++) {
                int s = __ldg(&bid[r]);
                if (s != cur) {
                    atomicAdd(&g_sums[cur * D + t], acc);
                    if (t == 0) atomicAdd(&g_cnt[cur], cnt);
                    acc = 0.0f; cnt = 0.0f; cur = s;
                }
                acc += x[(size_t)r * D + t];
                cnt += 1.0f;
            }
            atomicAdd(&g_sums[cur * D + t], acc);
            if (t == 0) atomicAdd(&g_cnt[cur], cnt);
        }
    }
    // All of this block's writes precede the trigger (program order).
    __syncthreads();
    cudaTriggerProgrammaticLaunchCompletion();
}

// ---------------------------------------------------------------------------
// MLPs: 32 blocks (one per segment) x 512 threads, weights L2-warm from the
// seg_sum prefetch blocks. PDL: launched early; blocks wait for seg grid via
// cudaGridDependencySynchronize before touching g_sums. Trigger at end lets
// the gate launch overlap this kernel's drain.
__device__ __forceinline__ void mlp_layer(
    const float* __restrict__ sin, float* __restrict__ sout,
    const float* __restrict__ W, const float* __restrict__ b,
    float (*sred)[D], int t128, int part, bool do_relu) {
    float p = 0.0f;
    const float* Wp = W + (part * 32) * D + t128;
    const float* xp = sin + part * 32;
#pragma unroll
    for (int k = 0; k < 32; k++)
        p = fmaf(xp[k], __ldg(&Wp[k * D]), p);
    sred[part][t128] = p;
    __syncthreads();
    if (part == 0) {
        float v = sred[0][t128] + sred[1][t128] + sred[2][t128] + sred[3][t128]
                + __ldg(&b[t128]);
        sout[t128] = do_relu ? fmaxf(v, 0.0f) : v;
    }
    __syncthreads();
}

__global__ void __launch_bounds__(512) mlp_kernel(
    const float* __restrict__ VW1, const float* __restrict__ Vb1,
    const float* __restrict__ VW2, const float* __restrict__ Vb2,
    const float* __restrict__ VW3, const float* __restrict__ Vb3,
    const float* __restrict__ EW1, const float* __restrict__ Eb1,
    const float* __restrict__ EW2, const float* __restrict__ Eb2,
    const float* __restrict__ EW3, const float* __restrict__ Eb3) {
    __shared__ float scv[D], bufA[D], bufB[D];
    __shared__ float sred[4][D];
    int seg = blockIdx.x;
    int t = threadIdx.x;
    int t128 = t & 127;
    int part = t >> 7;

    // Wait for the seg grid (and visibility of its atomics).
    cudaGridDependencySynchronize();

    if (t < D) {
        float cnt = fmaxf(g_cnt[seg], 1.0f);
        scv[t] = g_sums[seg * D + t] / cnt;
    }
    __syncthreads();

    // --- V MLP ---
    mlp_layer(scv,  bufA, VW1, Vb1, sred, t128, part, true);
    mlp_layer(bufA, bufB, VW2, Vb2, sred, t128, part, true);
    mlp_layer(bufB, bufA, VW3, Vb3, sred, t128, part, false);
    if (t < D) {
        float gV = 1.0f / (1.0f + expf(-bufA[t]));
        g_gateV[seg * D + t] = gV;
        bufB[t] = scv[t] * gV;     // c_V2 = c_V * gate_V (exact identity)
    }
    __syncthreads();

    // --- E MLP ---
    mlp_layer(bufB, bufA, EW1, Eb1, sred, t128, part, true);
    mlp_layer(bufA, bufB, EW2, Eb2, sred, t128, part, true);
    mlp_layer(bufB, bufA, EW3, Eb3, sred, t128, part, false);
    if (t < D) {
        g_gateE[seg * D + t] = 1.0f / (1.0f + expf(-bufA[t]));
        // restore scratch for the next launch (zero-invariant at entry)
        g_sums[seg * D + t] = 0.0f;
        if (t == 0) g_cnt[seg] = 0.0f;
    }
    __syncthreads();
    cudaTriggerProgrammaticLaunchCompletion();
}

// ---------------------------------------------------------------------------
// Gating. PDL: launched early; waits for the mlp grid before reading gates.
// Blocks [0, nodeBlocks) gate nodes (dst_na L2-warm); rest gate edges.
// 64 rows/block, 8 float4 iters; warp-uniform row -> bid/eidx broadcasts.
__global__ void __launch_bounds__(256) gate_kernel(
    const float* __restrict__ x, const float* __restrict__ ea,
    const int* __restrict__ eidx, const int* __restrict__ bid,
    float* __restrict__ outN, float* __restrict__ outE,
    int N, int E, int nodeBlocks) {
    int t = threadIdx.x;
    int b = blockIdx.x;

    // Wait for the mlp grid (gates ready + visible).
    cudaGridDependencySynchronize();

    if (b < nodeBlocks) {
        int r0 = b * GROWS;
        const float4* src = (const float4*)x;
        float4* dst = (float4*)outN;
        long long base = (long long)r0 * 32;
#pragma unroll
        for (int it = 0; it < 8; it++) {
            int i = it * 256 + t;
            int r = r0 + (i >> 5);             // warp-uniform
            if (r < N) {
                int s = __ldg(&bid[r]);        // broadcast
                float4 g = *(const float4*)&g_gateV[s * D + (i & 31) * 4];
                float4 v = src[base + i];
                v.x *= g.x; v.y *= g.y; v.z *= g.z; v.w *= g.w;
                __stcs(&dst[base + i], v);
            }
        }
    } else {
        int r0 = (b - nodeBlocks) * GROWS;
        const float4* src = (const float4*)ea;
        float4* dst = (float4*)outE;
        long long base = (long long)r0 * 32;
#pragma unroll
        for (int it = 0; it < 8; it++) {
            int i = it * 256 + t;
            int r = r0 + (i >> 5);             // warp-uniform
            if (r < E) {
                int s = __ldg(&bid[__ldg(&eidx[r])]);   // 2 broadcasts
                float4 g = *(const float4*)&g_gateE[s * D + (i & 31) * 4];
                float4 v = __ldcs(&src[base + i]);
                v.x *= g.x; v.y *= g.y; v.z *= g.z; v.w *= g.w;
                __stcs(&dst[base + i], v);
            }
        }
    }
}

// ---------------------------------------------------------------------------
extern "C" void kernel_launch(void* const* d_in, const int* in_sizes, int n_in,
                              void* d_out, int out_size) {
    const float* dst_na  = (const float*)d_in[0];
    const float* ea      = (const float*)d_in[1];
    const int*   eidx    = (const int*)d_in[2];   // [2, E], row 0 = src
    const int*   bid     = (const int*)d_in[3];
    const float* VW1 = (const float*)d_in[4];
    const float* Vb1 = (const float*)d_in[5];
    const float* VW2 = (const float*)d_in[6];
    const float* Vb2 = (const float*)d_in[7];
    const float* VW3 = (const float*)d_in[8];
    const float* Vb3 = (const float*)d_in[9];
    const float* EW1 = (const float*)d_in[10];
    const float* Eb1 = (const float*)d_in[11];
    const float* EW2 = (const float*)d_in[12];
    const float* Eb2 = (const float*)d_in[13];
    const float* EW3 = (const float*)d_in[14];
    const float* Eb3 = (const float*)d_in[15];

    int N = in_sizes[0] / D;
    int E = in_sizes[1] / D;
    float* out_nodes = (float*)d_out;
    float* out_edges = (float*)d_out + (size_t)N * D;

    int sumBlocks = (N + SROWS - 1) / SROWS;
    int nodeBlocks = (N + GROWS - 1) / GROWS;
    int edgeBlocks = (E + GROWS - 1) / GROWS;

    // Primary: plain launch.
    seg_sum_kernel<<<sumBlocks + 6, 256>>>(dst_na, bid, N, sumBlocks,
                                           VW1, VW2, VW3, EW1, EW2, EW3);

    // Secondary launches: PDL (programmatic stream serialization) so each
    // overlaps the predecessor's drain; device-side sync provides ordering.
    cudaLaunchAttribute pdlAttr;
    pdlAttr.id = cudaLaunchAttributeProgrammaticStreamSerialization;
    pdlAttr.val.programmaticStreamSerializationAllowed = 1;

    {
        cudaLaunchConfig_t cfg = {};
        cfg.gridDim = dim3(SEGS, 1, 1);
        cfg.blockDim = dim3(512, 1, 1);
        cfg.dynamicSmemBytes = 0;
        cfg.stream = 0;
        cfg.attrs = &pdlAttr;
        cfg.numAttrs = 1;
        cudaLaunchKernelEx(&cfg, mlp_kernel,
                           VW1, Vb1, VW2, Vb2, VW3, Vb3,
                           EW1, Eb1, EW2, Eb2, EW3, Eb3);
    }
    {
        cudaLaunchConfig_t cfg = {};
        cfg.gridDim = dim3(nodeBlocks + edgeBlocks, 1, 1);
        cfg.blockDim = dim3(256, 1, 1);
        cfg.dynamicSmemBytes = 0;
        cfg.stream = 0;
        cfg.attrs = &pdlAttr;
        cfg.numAttrs = 1;
        cudaLaunchKernelEx(&cfg, gate_kernel,
                           dst_na, ea, eidx, bid, out_nodes, out_edges,
                           N, E, nodeBlocks);
    }
}